// round 1
// baseline (speedup 1.0000x reference)
#include <cuda_runtime.h>

// Problem shape (fixed by reference setup_inputs): [B=64, S=2048, D=512] fp32
constexpr int B = 64;
constexpr int S = 2048;
constexpr int D = 512;
constexpr int D4 = D / 4;            // 128 float4 per row
constexpr int CHUNK = 16;            // timesteps per warp
constexpr int CHUNKS_PER_SEQ = S / CHUNK;  // 128
constexpr int THREADS = 256;         // 8 warps/block
constexpr int WARPS_PER_BLOCK = THREADS / 32;
constexpr int TOTAL_WARPS = B * CHUNKS_PER_SEQ;     // 8192
constexpr int GRID1 = TOTAL_WARPS / WARPS_PER_BLOCK; // 1024 blocks

// Kernel 1: unnormalized squared L2 of consecutive-row diffs.
// Each warp handles timesteps [s0, s0+CHUNK) of one batch, streaming rows
// so each input row is read ~once (prev row held in 4 float4 regs/lane).
__global__ void __launch_bounds__(THREADS)
l2_diff_kernel(const float4* __restrict__ x, float* __restrict__ out) {
    const int warp = (blockIdx.x * THREADS + threadIdx.x) >> 5;
    const int lane = threadIdx.x & 31;
    const int b    = warp / CHUNKS_PER_SEQ;
    const int s0   = (warp % CHUNKS_PER_SEQ) * CHUNK;

    const float4* base = x + (size_t)b * S * D4;

    // previous row: s0-1, except the very first chunk where d[0] = 0
    const int sprev = (s0 == 0) ? 0 : (s0 - 1);
    const float4* rowp = base + (size_t)sprev * D4;
    float4 prev[4];
    #pragma unroll
    for (int j = 0; j < 4; ++j) prev[j] = rowp[lane + 32 * j];

    if (s0 == 0 && lane == 0) out[(size_t)b * S] = 0.0f;

    const int s_start = (s0 == 0) ? 1 : s0;
    const int s_end   = s0 + CHUNK;

    for (int s = s_start; s < s_end; ++s) {
        const float4* row = base + (size_t)s * D4;
        float sum = 0.0f;
        #pragma unroll
        for (int j = 0; j < 4; ++j) {
            float4 c = row[lane + 32 * j];
            float dx = c.x - prev[j].x;
            float dy = c.y - prev[j].y;
            float dz = c.z - prev[j].z;
            float dw = c.w - prev[j].w;
            sum += dx * dx + dy * dy + dz * dz + dw * dw;
            prev[j] = c;
        }
        // warp reduce (sum over D)
        #pragma unroll
        for (int off = 16; off > 0; off >>= 1)
            sum += __shfl_xor_sync(0xffffffffu, sum, off);
        if (lane == 0) out[(size_t)b * S + s] = sum;
    }
}

// Kernel 2: per-batch max over S values, then divide in place.
__global__ void __launch_bounds__(256)
normalize_kernel(float* __restrict__ out) {
    const int b = blockIdx.x;
    float* row = out + (size_t)b * S;

    __shared__ float smax[256];
    float m = 0.0f;   // d >= 0 everywhere, so 0 is a valid identity
    for (int i = threadIdx.x; i < S; i += 256)
        m = fmaxf(m, row[i]);
    smax[threadIdx.x] = m;
    __syncthreads();
    #pragma unroll
    for (int w = 128; w > 0; w >>= 1) {
        if (threadIdx.x < w)
            smax[threadIdx.x] = fmaxf(smax[threadIdx.x], smax[threadIdx.x + w]);
        __syncthreads();
    }
    const float mx = smax[0];
    for (int i = threadIdx.x; i < S; i += 256)
        row[i] = row[i] / mx;
}

extern "C" void kernel_launch(void* const* d_in, const int* in_sizes, int n_in,
                              void* d_out, int out_size) {
    const float4* x = (const float4*)d_in[0];
    float* out = (float*)d_out;
    (void)in_sizes; (void)n_in; (void)out_size;

    l2_diff_kernel<<<GRID1, THREADS>>>(x, out);
    normalize_kernel<<<B, 256>>>(out);
}